// round 14
// baseline (speedup 1.0000x reference)
#include <cuda_runtime.h>
#include <cuda_fp16.h>

#define NT 512
#define EARB 144           // EA staging row stride bytes
#define PSB  144           // P staging row stride bytes
#define EXB  272           // exchange row stride bytes

// ---- edge-kernel smem layout ----
#define OFF_SC 0           // scale,shift,b1,b3 = 2048
#define OFF_W1 2048        // 8192
#define OFF_W2 10240       // 32768 (W2 chunk2 frags)
#define OFF_W3 43008       // 32768
#define OFF_EA 75776       // 8 pairs x 2304
#define OFF_EX 94208       // 8 pairs x 4352
#define OFF_P  129024      // 16 warps x 4608 (PR 2304 | PC 2304)
#define SMEM_E 202752

// ---- node-kernel smem layout ----
#define ARB  272
#define NOFF_A   0
#define NOFF_W   34816
#define NOFF_XS  100352
#define SMEM_N   165888

__device__ __align__(16) unsigned g_P[131072 * 128];
__device__ __align__(16) uint2 g_W1f[2 * 512];
__device__ __align__(16) uint2 g_W2f[24 * 512];
__device__ __align__(16) uint2 g_W3f[8 * 512];

#define CP16(dst, src)  asm volatile("cp.async.cg.shared.global [%0], [%1], 16;" :: "r"(dst), "l"(src) : "memory")
#define CP_COMMIT()     asm volatile("cp.async.commit_group;" ::: "memory")
#define CP_WAIT(n)      asm volatile("cp.async.wait_group %0;" :: "n"(n) : "memory")

__device__ __forceinline__ unsigned smem_u32(const void* p) {
    unsigned a;
    asm("{ .reg .u64 t; cvta.to.shared.u64 t, %1; cvt.u32.u64 %0, t; }" : "=r"(a) : "l"(p));
    return a;
}
__device__ __forceinline__ unsigned f22h2(float lo, float hi) {
    unsigned r;
    asm("cvt.rn.f16x2.f32 %0, %1, %2;" : "=r"(r) : "f"(hi), "f"(lo));
    return r;
}
__device__ __forceinline__ float2 h2f2(unsigned u) {
    __half2 h; *(unsigned*)&h = u;
    return __half22float2(h);
}
__device__ __forceinline__ void mma16(float* c, unsigned a0, unsigned a1, unsigned a2,
                                      unsigned a3, unsigned b0, unsigned b1) {
    asm volatile("mma.sync.aligned.m16n8k16.row.col.f32.f16.f16.f32 "
        "{%0,%1,%2,%3}, {%4,%5,%6,%7}, {%8,%9}, {%0,%1,%2,%3};"
        : "+f"(c[0]), "+f"(c[1]), "+f"(c[2]), "+f"(c[3])
        : "r"(a0), "r"(a1), "r"(a2), "r"(a3), "r"(b0), "r"(b1));
}
__device__ __forceinline__ float tanh_mufu(float v) {
    float r;
    asm("tanh.approx.f32 %0, %1;" : "=f"(r) : "f"(v));
    return r;
}
__device__ __forceinline__ void st_cs_v2(float* p, float a, float b) {
    asm volatile("st.global.cs.v2.f32 [%0], {%1,%2};" :: "l"(p), "f"(a), "f"(b) : "memory");
}
__device__ __forceinline__ unsigned lds32(unsigned a) {
    unsigned v; asm volatile("ld.shared.b32 %0, [%1];" : "=r"(v) : "r"(a)); return v;
}
__device__ __forceinline__ void sts32(unsigned a, unsigned v) {
    asm volatile("st.shared.b32 [%0], %1;" :: "r"(a), "r"(v) : "memory");
}

// ---- prep: weights -> fragment-major fp16 ----
__global__ void prep(const float* __restrict__ W1, const float* __restrict__ W2,
                     const float* __restrict__ W3) {
    int t = blockIdx.x * blockDim.x + threadIdx.x;
    int s = gridDim.x * blockDim.x;
    for (int i = t; i < 2 * 512; i += s) {
        int lane = i & 31, nt = (i >> 5) & 3, cq = (i >> 7) & 3, ks = i >> 9;
        int n = cq * 32 + nt * 8 + (lane >> 2), k0 = ks * 16 + (lane & 3) * 2;
        g_W1f[i] = make_uint2(f22h2(W1[k0 * 128 + n], W1[(k0 + 1) * 128 + n]),
                              f22h2(W1[(k0 + 8) * 128 + n], W1[(k0 + 9) * 128 + n]));
    }
    for (int i = t; i < 24 * 512; i += s) {
        int lane = i & 31, nt = (i >> 5) & 3, cq = (i >> 7) & 3, ks = i >> 9;
        int n = cq * 32 + nt * 8 + (lane >> 2), k0 = ks * 16 + (lane & 3) * 2;
        g_W2f[i] = make_uint2(f22h2(W2[k0 * 128 + n], W2[(k0 + 1) * 128 + n]),
                              f22h2(W2[(k0 + 8) * 128 + n], W2[(k0 + 9) * 128 + n]));
    }
    for (int i = t; i < 8 * 512; i += s) {
        int lane = i & 31, nt = (i >> 5) & 3, cq = (i >> 7) & 3, ks = i >> 9;
        int n = cq * 32 + nt * 8 + (lane >> 2), k0 = ks * 16 + (lane & 3) * 2;
        g_W3f[i] = make_uint2(f22h2(W3[k0 * 128 + n], W3[(k0 + 1) * 128 + n]),
                              f22h2(W3[(k0 + 8) * 128 + n], W3[(k0 + 9) * 128 + n]));
    }
}

// ---- node projections: persistent; P[n] = x[n] @ [W2c0 | W2c1] ----
__global__ void __launch_bounds__(512, 1)
node_proj(const float* __restrict__ x, int N, int ntilesN) {
    extern __shared__ char smem[];
    const unsigned sb = smem_u32(smem);
    const int tid = threadIdx.x;
    const int w = tid >> 5, lane = tid & 31;
    const int gid = lane >> 2, tig = lane & 3;
    const int rb = (w >> 2) * 32, cq = w & 3, cbase = cq * 32;
    const int r4 = tid >> 2, q4 = tid & 3;

    #pragma unroll
    for (int i = 0; i < 8; i++)
        CP16(sb + NOFF_W + (i * 512 + tid) * 16, (const char*)g_W2f + (i * 512 + tid) * 16);
    CP_COMMIT(); CP_WAIT(0);
    __syncthreads();

    const char* Ath = smem + NOFF_A + (rb + gid) * ARB + tig * 4;
    const uint2* Wt = (const uint2*)(smem + NOFF_W) + cq * 128 + lane;

    for (int tile = blockIdx.x; tile < ntilesN; tile += gridDim.x) {
        {
            int node = min(tile * 128 + r4, N - 1);
            const float* s = x + (long long)node * 128 + q4 * 32;
            unsigned d = sb + NOFF_XS + (r4 * 128 + q4 * 32) * 4;
            #pragma unroll
            for (int i = 0; i < 8; i++) CP16(d + i * 16, s + i * 4);
        }
        CP_COMMIT(); CP_WAIT(0);
        __syncthreads();
        {
            const float* s = (const float*)(smem + NOFF_XS) + r4 * 128 + q4 * 32;
            unsigned* d = (unsigned*)(smem + NOFF_A + r4 * ARB) + q4 * 16;
            #pragma unroll
            for (int i = 0; i < 16; i++) d[i] = f22h2(s[2 * i], s[2 * i + 1]);
        }
        __syncthreads();

        float acc[2][4][4];
        #pragma unroll
        for (int ch = 0; ch < 2; ch++) {
            #pragma unroll
            for (int m = 0; m < 2; m++)
                #pragma unroll
                for (int n = 0; n < 4; n++)
                    { acc[m][n][0]=0.f; acc[m][n][1]=0.f; acc[m][n][2]=0.f; acc[m][n][3]=0.f; }
            #pragma unroll
            for (int ks = 0; ks < 8; ks++) {
                unsigned a[2][4];
                #pragma unroll
                for (int mt = 0; mt < 2; mt++) {
                    const char* Am = Ath + ks * 32 + mt * 16 * ARB;
                    a[mt][0] = *(const unsigned*)(Am);
                    a[mt][1] = *(const unsigned*)(Am + 8 * ARB);
                    a[mt][2] = *(const unsigned*)(Am + 16);
                    a[mt][3] = *(const unsigned*)(Am + 8 * ARB + 16);
                }
                const uint2* Bk = Wt + (ch * 8 + ks) * 512;
                #pragma unroll
                for (int nt = 0; nt < 4; nt++) {
                    uint2 b = Bk[nt * 32];
                    mma16(acc[0][nt], a[0][0], a[0][1], a[0][2], a[0][3], b.x, b.y);
                    mma16(acc[1][nt], a[1][0], a[1][1], a[1][2], a[1][3], b.x, b.y);
                }
            }
            #pragma unroll
            for (int mt = 0; mt < 2; mt++) {
                int node0 = tile * 128 + rb + mt * 16 + gid;
                int pcol = ch * 64 + (cbase >> 1) + tig;
                #pragma unroll
                for (int nt = 0; nt < 4; nt++) {
                    if (node0 < N)
                        g_P[(long long)node0 * 128 + pcol + nt * 4] =
                            f22h2(acc[mt][nt][0], acc[mt][nt][1]);
                    if (node0 + 8 < N)
                        g_P[(long long)(node0 + 8) * 128 + pcol + nt * 4] =
                            f22h2(acc[mt][nt][2], acc[mt][nt][3]);
                }
            }
        }
        __syncthreads();
    }
}

// ---- edge kernel: 512 threads, 8 warp-pairs, 16 edges x 64 cols per warp ----
__global__ void __launch_bounds__(NT, 1)
edge_kernel(const int* __restrict__ ei, const float* __restrict__ ea,
            const float* __restrict__ b1, const float* __restrict__ b2,
            const float* __restrict__ gamma, const float* __restrict__ beta,
            const float* __restrict__ mean, const float* __restrict__ var,
            const float* __restrict__ b3,
            float* __restrict__ out, int E, int nchunks)
{
    extern __shared__ char smem[];
    const unsigned sb = smem_u32(smem);
    float* sScale = (float*)(smem + OFF_SC);
    float* sShift = (float*)(smem + OFF_SC + 512);
    float* sB1    = (float*)(smem + OFF_SC + 1024);
    float* sB3    = (float*)(smem + OFF_SC + 1536);

    const int tid = threadIdx.x;
    const int w = tid >> 5, lane = tid & 31;
    const int pair = w >> 1, s = w & 1;
    const int gid = lane >> 2, tig = lane & 3;
    const int l16 = lane & 15;

    #define PBAR() asm volatile("bar.sync %0, 64;" :: "r"(pair + 1) : "memory")

    if (tid < 128) {
        float sc = gamma[tid] * rsqrtf(var[tid] + 1e-5f);
        sScale[tid] = sc;
        sShift[tid] = (b2[tid] - mean[tid]) * sc + beta[tid];
        sB1[tid] = b1[tid];
        sB3[tid] = b3[tid];
    }
    for (int i = tid; i < 512; i += NT)
        CP16(sb + OFF_W1 + i * 16, (const char*)g_W1f + i * 16);
    for (int i = tid; i < 2048; i += NT)
        CP16(sb + OFF_W2 + i * 16, (const char*)(g_W2f + 16 * 512) + i * 16);
    for (int i = tid; i < 2048; i += NT)
        CP16(sb + OFF_W3 + i * 16, (const char*)g_W3f + i * 16);
    CP_COMMIT(); CP_WAIT(0);
    __syncthreads();

    const bool is64 = ((ei[1] | ei[3] | ei[5] | ei[7]) == 0);
    const long long* ei64 = (const long long*)ei;

    const unsigned sEA = sb + OFF_EA + pair * 2304;
    const unsigned sEX = sb + OFF_EX + pair * 4352;
    const unsigned sPR = sb + OFF_P + w * 4608;
    const unsigned sPC = sPR + 2304;
    const char* pEA = smem + OFF_EA + pair * 2304;
    // weight frag pointers pre-offset by side: cq = 2s..2s+1
    const uint2* W1t = (const uint2*)(smem + OFF_W1) + s * 256 + lane;
    const uint2* W2t = (const uint2*)(smem + OFF_W2) + s * 256 + lane;
    const uint2* W3t = (const uint2*)(smem + OFF_W3) + s * 256 + lane;

    #define LDIDX(dst, eb) { int _e = min((eb) + l16, E - 1); \
        long long _o = (lane < 16) ? (long long)_e : (long long)E + _e; \
        (dst) = is64 ? (int)ei64[_o] : ei[_o]; }
    // warp s loads EA rows s*8..s*8+7 of the pair tile
    #define ISSUE_EA(eb) { int _r = s * 8 + (lane >> 2); int _q = lane & 3; \
        int _ge = min((eb) + _r, E - 1); \
        const float* _s = ea + (long long)_ge * 32 + _q * 8; \
        unsigned _d = sEA + _r * EARB + _q * 32; \
        CP16(_d, _s); CP16(_d + 16, _s + 4); CP_COMMIT(); }

    const int stride = gridDim.x * 8;
    const int c0 = blockIdx.x * 8 + pair;

    int idxv;
    LDIDX(idxv, c0 * 16);
    ISSUE_EA(c0 * 16);                       // group A: EA(cur) half

    float acc[8][4];
    unsigned ef[32], pe[16];

    for (int c = c0; c < nchunks; c += stride) {
        const int ebase = c * 16;

        // issue P gather for cur (own col-half of both PR and PC)
        {
            int node = lane >> 1, part = lane & 1;
            int nR = __shfl_sync(0xffffffffu, idxv, node);
            int nC = __shfl_sync(0xffffffffu, idxv, 16 + node);
            const char* srcR = (const char*)g_P + (long long)nR * 512 + s * 128 + part * 64;
            const char* srcC = (const char*)g_P + (long long)nC * 512 + 256 + s * 128 + part * 64;
            unsigned dR = sPR + node * PSB + part * 64;
            unsigned dC = sPC + node * PSB + part * 64;
            #pragma unroll
            for (int i = 0; i < 4; i++) CP16(dR + i * 16, srcR + i * 16);
            #pragma unroll
            for (int i = 0; i < 4; i++) CP16(dC + i * 16, srcC + i * 16);
            CP_COMMIT();                     // group B: P(cur)
        }
        CP_WAIT(1);                          // EA(cur) own half done
        PBAR();                              // both halves visible

        // MMA1: e(own 64 cols) = EA @ W1
        #pragma unroll
        for (int j = 0; j < 8; j++) { acc[j][0]=0.f; acc[j][1]=0.f; acc[j][2]=0.f; acc[j][3]=0.f; }
        #pragma unroll
        for (int ks = 0; ks < 2; ks++) {
            float2 v0 = *(const float2*)(pEA + gid * EARB + ks * 64 + tig * 8);
            float2 v1 = *(const float2*)(pEA + (gid + 8) * EARB + ks * 64 + tig * 8);
            float2 v2 = *(const float2*)(pEA + gid * EARB + ks * 64 + 32 + tig * 8);
            float2 v3 = *(const float2*)(pEA + (gid + 8) * EARB + ks * 64 + 32 + tig * 8);
            unsigned a0 = f22h2(v0.x, v0.y), a1 = f22h2(v1.x, v1.y);
            unsigned a2 = f22h2(v2.x, v2.y), a3 = f22h2(v3.x, v3.y);
            #pragma unroll
            for (int j = 0; j < 8; j++) {
                uint2 b = W1t[ks * 512 + (j >> 2) * 128 + (j & 3) * 32];
                mma16(acc[j], a0, a1, a2, a3, b.x, b.y);
            }
        }

        // epi1: tanh -> pe; write own half to exchange
        #pragma unroll
        for (int j = 0; j < 8; j++) {
            int cc = s * 64 + j * 8 + 2 * tig;
            float2 bb = *(const float2*)(sB1 + cc);
            pe[2*j]   = f22h2(tanh_mufu(acc[j][0] + bb.x), tanh_mufu(acc[j][1] + bb.y));
            pe[2*j+1] = f22h2(tanh_mufu(acc[j][2] + bb.x), tanh_mufu(acc[j][3] + bb.y));
            sts32(sEX + gid * EXB + cc * 2, pe[2*j]);
            sts32(sEX + (gid + 8) * EXB + cc * 2, pe[2*j+1]);
        }
        PBAR();                              // e complete in exchange
        // assemble full-K e frags: own from pe, partner from exchange
        #pragma unroll
        for (int jj = 0; jj < 4; jj++) {
            int kso = s * 4 + jj;
            ef[4*kso+0] = pe[4*jj];   ef[4*kso+1] = pe[4*jj+1];
            ef[4*kso+2] = pe[4*jj+2]; ef[4*kso+3] = pe[4*jj+3];
            int ksp = (1 - s) * 4 + jj;
            unsigned base = sEX + ksp * 32 + 4 * tig;
            ef[4*ksp+0] = lds32(base + gid * EXB);
            ef[4*ksp+1] = lds32(base + (gid + 8) * EXB);
            ef[4*ksp+2] = lds32(base + gid * EXB + 16);
            ef[4*ksp+3] = lds32(base + (gid + 8) * EXB + 16);
        }

        // prefetch next chunk EA + indices
        int cn = c + stride;
        int nb = (cn < nchunks ? cn : c) * 16;
        ISSUE_EA(nb);                        // group A': EA(next)
        LDIDX(idxv, nb);

        // MMA2: h(own cols) = e @ W2c2 (K=128)
        #pragma unroll
        for (int j = 0; j < 8; j++) { acc[j][0]=0.f; acc[j][1]=0.f; acc[j][2]=0.f; acc[j][3]=0.f; }
        #pragma unroll
        for (int ks = 0; ks < 8; ks++) {
            #pragma unroll
            for (int j = 0; j < 8; j++) {
                uint2 b = W2t[ks * 512 + (j >> 2) * 128 + (j & 3) * 32];
                mma16(acc[j], ef[4*ks], ef[4*ks+1], ef[4*ks+2], ef[4*ks+3], b.x, b.y);
            }
        }
        CP_WAIT(1);                          // P(cur) done (EA next outstanding)
        __syncwarp();

        // epi2: h = relu((acc + Pr + Pc)*scale + shift) -> pe
        #pragma unroll
        for (int j = 0; j < 8; j++) {
            int cc = s * 64 + j * 8 + 2 * tig;
            float2 sc = *(const float2*)(sScale + cc);
            float2 sh = *(const float2*)(sShift + cc);
            int po = j * 16 + tig * 4;
            float2 r0 = h2f2(lds32(sPR + gid * PSB + po));
            float2 q0 = h2f2(lds32(sPC + gid * PSB + po));
            float2 r1 = h2f2(lds32(sPR + (gid + 8) * PSB + po));
            float2 q1 = h2f2(lds32(sPC + (gid + 8) * PSB + po));
            pe[2*j] = f22h2(
                fmaxf(fmaf(acc[j][0] + r0.x + q0.x, sc.x, sh.x), 0.f),
                fmaxf(fmaf(acc[j][1] + r0.y + q0.y, sc.y, sh.y), 0.f));
            pe[2*j+1] = f22h2(
                fmaxf(fmaf(acc[j][2] + r1.x + q1.x, sc.x, sh.x), 0.f),
                fmaxf(fmaf(acc[j][3] + r1.y + q1.y, sc.y, sh.y), 0.f));
        }
        PBAR();                              // partner done reading e
        #pragma unroll
        for (int j = 0; j < 8; j++) {
            int cc = s * 64 + j * 8 + 2 * tig;
            sts32(sEX + gid * EXB + cc * 2, pe[2*j]);
            sts32(sEX + (gid + 8) * EXB + cc * 2, pe[2*j+1]);
        }
        PBAR();                              // h complete in exchange
        #pragma unroll
        for (int jj = 0; jj < 4; jj++) {
            int kso = s * 4 + jj;
            ef[4*kso+0] = pe[4*jj];   ef[4*kso+1] = pe[4*jj+1];
            ef[4*kso+2] = pe[4*jj+2]; ef[4*kso+3] = pe[4*jj+3];
            int ksp = (1 - s) * 4 + jj;
            unsigned base = sEX + ksp * 32 + 4 * tig;
            ef[4*ksp+0] = lds32(base + gid * EXB);
            ef[4*ksp+1] = lds32(base + (gid + 8) * EXB);
            ef[4*ksp+2] = lds32(base + gid * EXB + 16);
            ef[4*ksp+3] = lds32(base + (gid + 8) * EXB + 16);
        }

        // MMA3: y(own cols) = h @ W3
        #pragma unroll
        for (int j = 0; j < 8; j++) { acc[j][0]=0.f; acc[j][1]=0.f; acc[j][2]=0.f; acc[j][3]=0.f; }
        #pragma unroll
        for (int ks = 0; ks < 8; ks++) {
            #pragma unroll
            for (int j = 0; j < 8; j++) {
                uint2 b = W3t[ks * 512 + (j >> 2) * 128 + (j & 3) * 32];
                mma16(acc[j], ef[4*ks], ef[4*ks+1], ef[4*ks+2], ef[4*ks+3], b.x, b.y);
            }
        }

        // epi3: relu(y + b3) -> gmem
        {
            int e0 = ebase + gid, e1 = ebase + gid + 8;
            float* po0 = out + (long long)e0 * 128;
            float* po1 = out + (long long)e1 * 128;
            #pragma unroll
            for (int j = 0; j < 8; j++) {
                int cc = s * 64 + j * 8 + 2 * tig;
                float2 bb = *(const float2*)(sB3 + cc);
                if (e0 < E) st_cs_v2(po0 + cc, fmaxf(acc[j][0] + bb.x, 0.f),
                                               fmaxf(acc[j][1] + bb.y, 0.f));
                if (e1 < E) st_cs_v2(po1 + cc, fmaxf(acc[j][2] + bb.x, 0.f),
                                               fmaxf(acc[j][3] + bb.y, 0.f));
            }
        }
    }
    CP_WAIT(0);
}

extern "C" void kernel_launch(void* const* d_in, const int* in_sizes, int n_in,
                              void* d_out, int out_size) {
    const float* x     = (const float*)d_in[0];
    const int*   ei    = (const int*)  d_in[1];
    const float* eattr = (const float*)d_in[2];
    const float* W1    = (const float*)d_in[3];
    const float* b1    = (const float*)d_in[4];
    const float* W2    = (const float*)d_in[5];
    const float* b2    = (const float*)d_in[6];
    const float* gam   = (const float*)d_in[7];
    const float* bet   = (const float*)d_in[8];
    const float* mean  = (const float*)d_in[9];
    const float* var   = (const float*)d_in[10];
    const float* W3    = (const float*)d_in[11];
    const float* b3    = (const float*)d_in[12];
    float* out = (float*)d_out;

    int N = in_sizes[0] / 128;
    int E = in_sizes[2] / 32;
    int nchunks = (E + 15) / 16;
    int ntilesN = (N + 127) / 128;

    cudaFuncSetAttribute(node_proj, cudaFuncAttributeMaxDynamicSharedMemorySize, SMEM_N);
    cudaFuncSetAttribute(edge_kernel, cudaFuncAttributeMaxDynamicSharedMemorySize, SMEM_E);

    prep<<<64, 256>>>(W1, W2, W3);
    node_proj<<<148, 512, SMEM_N>>>(x, N, ntilesN);
    edge_kernel<<<148, NT, SMEM_E>>>(ei, eattr, b1, b2, gam, bet,
                                     mean, var, b3, out, E, nchunks);
}

// round 15
// speedup vs baseline: 1.1500x; 1.1500x over previous
#include <cuda_runtime.h>
#include <cuda_fp16.h>

#define NT 448
#define PRB  272           // P staging row stride
#define WPB  8704          // per-warp staging (PR 4352 | PC 4352)

// ---- edge-kernel smem layout ----
#define OFF_SC 0           // scale,shift,b1,b3 = 2048
#define OFF_W1 2048        // 8192
#define OFF_W2 10240       // 32768 (W2 chunk2 frags)
#define OFF_W3 43008       // 32768
#define OFF_P  75776       // 14 warps x 8704
#define SMEM_E (75776 + 14 * 8704)

// ---- node-kernel smem layout ----
#define ARB  272
#define NOFF_A   0
#define NOFF_W   34816
#define NOFF_XS  100352
#define SMEM_N   165888

__device__ __align__(16) unsigned g_P[131072 * 128];
__device__ __align__(16) uint2 g_W1f[2 * 512];
__device__ __align__(16) uint2 g_W2f[24 * 512];
__device__ __align__(16) uint2 g_W3f[8 * 512];

#define CP16(dst, src)  asm volatile("cp.async.cg.shared.global [%0], [%1], 16;" :: "r"(dst), "l"(src) : "memory")
#define CP_COMMIT()     asm volatile("cp.async.commit_group;" ::: "memory")
#define CP_WAIT(n)      asm volatile("cp.async.wait_group %0;" :: "n"(n) : "memory")

__device__ __forceinline__ unsigned smem_u32(const void* p) {
    unsigned a;
    asm("{ .reg .u64 t; cvta.to.shared.u64 t, %1; cvt.u32.u64 %0, t; }" : "=r"(a) : "l"(p));
    return a;
}
__device__ __forceinline__ unsigned f22h2(float lo, float hi) {
    unsigned r;
    asm("cvt.rn.f16x2.f32 %0, %1, %2;" : "=r"(r) : "f"(hi), "f"(lo));
    return r;
}
__device__ __forceinline__ float2 h2f2(unsigned u) {
    __half2 h; *(unsigned*)&h = u;
    return __half22float2(h);
}
__device__ __forceinline__ void mma16(float* c, unsigned a0, unsigned a1, unsigned a2,
                                      unsigned a3, unsigned b0, unsigned b1) {
    asm volatile("mma.sync.aligned.m16n8k16.row.col.f32.f16.f16.f32 "
        "{%0,%1,%2,%3}, {%4,%5,%6,%7}, {%8,%9}, {%0,%1,%2,%3};"
        : "+f"(c[0]), "+f"(c[1]), "+f"(c[2]), "+f"(c[3])
        : "r"(a0), "r"(a1), "r"(a2), "r"(a3), "r"(b0), "r"(b1));
}
__device__ __forceinline__ float tanh_mufu(float v) {
    float r;
    asm("tanh.approx.f32 %0, %1;" : "=f"(r) : "f"(v));
    return r;
}
__device__ __forceinline__ void st_cs_v2(float* p, float a, float b) {
    asm volatile("st.global.cs.v2.f32 [%0], {%1,%2};" :: "l"(p), "f"(a), "f"(b) : "memory");
}

// ---- prep: weights -> fragment-major fp16 ----
__global__ void prep(const float* __restrict__ W1, const float* __restrict__ W2,
                     const float* __restrict__ W3) {
    int t = blockIdx.x * blockDim.x + threadIdx.x;
    int s = gridDim.x * blockDim.x;
    for (int i = t; i < 2 * 512; i += s) {
        int lane = i & 31, nt = (i >> 5) & 3, cq = (i >> 7) & 3, ks = i >> 9;
        int n = cq * 32 + nt * 8 + (lane >> 2), k0 = ks * 16 + (lane & 3) * 2;
        g_W1f[i] = make_uint2(f22h2(W1[k0 * 128 + n], W1[(k0 + 1) * 128 + n]),
                              f22h2(W1[(k0 + 8) * 128 + n], W1[(k0 + 9) * 128 + n]));
    }
    for (int i = t; i < 24 * 512; i += s) {
        int lane = i & 31, nt = (i >> 5) & 3, cq = (i >> 7) & 3, ks = i >> 9;
        int n = cq * 32 + nt * 8 + (lane >> 2), k0 = ks * 16 + (lane & 3) * 2;
        g_W2f[i] = make_uint2(f22h2(W2[k0 * 128 + n], W2[(k0 + 1) * 128 + n]),
                              f22h2(W2[(k0 + 8) * 128 + n], W2[(k0 + 9) * 128 + n]));
    }
    for (int i = t; i < 8 * 512; i += s) {
        int lane = i & 31, nt = (i >> 5) & 3, cq = (i >> 7) & 3, ks = i >> 9;
        int n = cq * 32 + nt * 8 + (lane >> 2), k0 = ks * 16 + (lane & 3) * 2;
        g_W3f[i] = make_uint2(f22h2(W3[k0 * 128 + n], W3[(k0 + 1) * 128 + n]),
                              f22h2(W3[(k0 + 8) * 128 + n], W3[(k0 + 9) * 128 + n]));
    }
}

// ---- node projections: persistent; P[n] = x[n] @ [W2c0 | W2c1] ----
__global__ void __launch_bounds__(512, 1)
node_proj(const float* __restrict__ x, int N, int ntilesN) {
    extern __shared__ char smem[];
    const unsigned sb = smem_u32(smem);
    const int tid = threadIdx.x;
    const int w = tid >> 5, lane = tid & 31;
    const int gid = lane >> 2, tig = lane & 3;
    const int rb = (w >> 2) * 32, cq = w & 3, cbase = cq * 32;
    const int r4 = tid >> 2, q4 = tid & 3;

    #pragma unroll
    for (int i = 0; i < 8; i++)
        CP16(sb + NOFF_W + (i * 512 + tid) * 16, (const char*)g_W2f + (i * 512 + tid) * 16);
    CP_COMMIT(); CP_WAIT(0);
    __syncthreads();

    const char* Ath = smem + NOFF_A + (rb + gid) * ARB + tig * 4;
    const uint2* Wt = (const uint2*)(smem + NOFF_W) + cq * 128 + lane;

    for (int tile = blockIdx.x; tile < ntilesN; tile += gridDim.x) {
        {
            int node = min(tile * 128 + r4, N - 1);
            const float* s = x + (long long)node * 128 + q4 * 32;
            unsigned d = sb + NOFF_XS + (r4 * 128 + q4 * 32) * 4;
            #pragma unroll
            for (int i = 0; i < 8; i++) CP16(d + i * 16, s + i * 4);
        }
        CP_COMMIT(); CP_WAIT(0);
        __syncthreads();
        {
            const float* s = (const float*)(smem + NOFF_XS) + r4 * 128 + q4 * 32;
            unsigned* d = (unsigned*)(smem + NOFF_A + r4 * ARB) + q4 * 16;
            #pragma unroll
            for (int i = 0; i < 16; i++) d[i] = f22h2(s[2 * i], s[2 * i + 1]);
        }
        __syncthreads();

        float acc[2][4][4];
        #pragma unroll
        for (int ch = 0; ch < 2; ch++) {
            #pragma unroll
            for (int m = 0; m < 2; m++)
                #pragma unroll
                for (int n = 0; n < 4; n++)
                    { acc[m][n][0]=0.f; acc[m][n][1]=0.f; acc[m][n][2]=0.f; acc[m][n][3]=0.f; }
            #pragma unroll
            for (int ks = 0; ks < 8; ks++) {
                unsigned a[2][4];
                #pragma unroll
                for (int mt = 0; mt < 2; mt++) {
                    const char* Am = Ath + ks * 32 + mt * 16 * ARB;
                    a[mt][0] = *(const unsigned*)(Am);
                    a[mt][1] = *(const unsigned*)(Am + 8 * ARB);
                    a[mt][2] = *(const unsigned*)(Am + 16);
                    a[mt][3] = *(const unsigned*)(Am + 8 * ARB + 16);
                }
                const uint2* Bk = Wt + (ch * 8 + ks) * 512;
                #pragma unroll
                for (int nt = 0; nt < 4; nt++) {
                    uint2 b = Bk[nt * 32];
                    mma16(acc[0][nt], a[0][0], a[0][1], a[0][2], a[0][3], b.x, b.y);
                    mma16(acc[1][nt], a[1][0], a[1][1], a[1][2], a[1][3], b.x, b.y);
                }
            }
            #pragma unroll
            for (int mt = 0; mt < 2; mt++) {
                int node0 = tile * 128 + rb + mt * 16 + gid;
                int pcol = ch * 64 + (cbase >> 1) + tig;
                #pragma unroll
                for (int nt = 0; nt < 4; nt++) {
                    if (node0 < N)
                        g_P[(long long)node0 * 128 + pcol + nt * 4] =
                            f22h2(acc[mt][nt][0], acc[mt][nt][1]);
                    if (node0 + 8 < N)
                        g_P[(long long)(node0 + 8) * 128 + pcol + nt * 4] =
                            f22h2(acc[mt][nt][2], acc[mt][nt][3]);
                }
            }
        }
        __syncthreads();
    }
}

// ---- edge kernel: 14 warps, barrier-free, 16 edges x 128 cols per warp ----
__global__ void __launch_bounds__(NT, 1)
edge_kernel(const int* __restrict__ ei, const float* __restrict__ ea,
            const float* __restrict__ b1, const float* __restrict__ b2,
            const float* __restrict__ gamma, const float* __restrict__ beta,
            const float* __restrict__ mean, const float* __restrict__ var,
            const float* __restrict__ b3,
            float* __restrict__ out, int E, int nchunks)
{
    extern __shared__ char smem[];
    const unsigned sb = smem_u32(smem);
    float* sScale = (float*)(smem + OFF_SC);
    float* sShift = (float*)(smem + OFF_SC + 512);
    float* sB1    = (float*)(smem + OFF_SC + 1024);
    float* sB3    = (float*)(smem + OFF_SC + 1536);

    const int tid = threadIdx.x;
    const int w = tid >> 5, lane = tid & 31;
    const int gid = lane >> 2, tig = lane & 3;
    const int l16 = lane & 15, lh = lane >> 4;

    if (tid < 128) {
        float sc = gamma[tid] * rsqrtf(var[tid] + 1e-5f);
        sScale[tid] = sc;
        sShift[tid] = (b2[tid] - mean[tid]) * sc + beta[tid];
        sB1[tid] = b1[tid];
        sB3[tid] = b3[tid];
    }
    for (int i = tid; i < 512; i += NT)
        CP16(sb + OFF_W1 + i * 16, (const char*)g_W1f + i * 16);
    for (int i = tid; i < 2048; i += NT)
        CP16(sb + OFF_W2 + i * 16, (const char*)(g_W2f + 16 * 512) + i * 16);
    for (int i = tid; i < 2048; i += NT)
        CP16(sb + OFF_W3 + i * 16, (const char*)g_W3f + i * 16);
    CP_COMMIT(); CP_WAIT(0);
    __syncthreads();

    const bool is64 = ((ei[1] | ei[3] | ei[5] | ei[7]) == 0);
    const long long* ei64 = (const long long*)ei;

    // per-warp P staging
    const unsigned sPR = sb + OFF_P + w * WPB;
    const unsigned sPC = sPR + 4352;
    const uint2* W1t = (const uint2*)(smem + OFF_W1) + lane;
    const uint2* W2t = (const uint2*)(smem + OFF_W2) + lane;
    const uint2* W3t = (const uint2*)(smem + OFF_W3) + lane;

    #define LDIDX(dst, eb) { int _e = min((eb) + l16, E - 1); \
        long long _o = (lane < 16) ? (long long)_e : (long long)E + _e; \
        (dst) = is64 ? (int)ei64[_o] : ei[_o]; }
    // EA fragment LDG: each lane loads exactly its 8 mma A-frag float2s
    #define LDG_EA(eb) { \
        int _g0 = min((eb) + gid, E - 1), _g1 = min((eb) + gid + 8, E - 1); \
        const float2* _p0 = (const float2*)(ea + (long long)_g0 * 32) + tig; \
        const float2* _p1 = (const float2*)(ea + (long long)_g1 * 32) + tig; \
        eaf[0] = __ldg(_p0);      eaf[1] = __ldg(_p1); \
        eaf[2] = __ldg(_p0 + 4);  eaf[3] = __ldg(_p1 + 4); \
        eaf[4] = __ldg(_p0 + 8);  eaf[5] = __ldg(_p1 + 8); \
        eaf[6] = __ldg(_p0 + 12); eaf[7] = __ldg(_p1 + 12); }

    const int stride = gridDim.x * 14;
    const int c0 = blockIdx.x * 14 + w;

    int idxv;
    float2 eaf[8];
    LDIDX(idxv, c0 * 16);
    LDG_EA(c0 * 16);

    float acc[16][4];
    unsigned ef[32];

    for (int c = c0; c < nchunks; c += stride) {
        const int ebase = c * 16;

        // issue P gather (only cp.async group in flight)
        {
            int nR = __shfl_sync(0xffffffffu, idxv, l16);
            int nC = __shfl_sync(0xffffffffu, idxv, 16 + l16);
            const char* srcR = (const char*)g_P + (long long)nR * 512 + lh * 128;
            const char* srcC = (const char*)g_P + (long long)nC * 512 + 256 + lh * 128;
            unsigned dR = sPR + l16 * PRB + lh * 128;
            unsigned dC = sPC + l16 * PRB + lh * 128;
            #pragma unroll
            for (int i = 0; i < 8; i++) CP16(dR + i * 16, srcR + i * 16);
            #pragma unroll
            for (int i = 0; i < 8; i++) CP16(dC + i * 16, srcC + i * 16);
            CP_COMMIT();
        }

        // MMA1: e = EA @ W1 (K=32), frags from registers
        #pragma unroll
        for (int j = 0; j < 16; j++) { acc[j][0]=0.f; acc[j][1]=0.f; acc[j][2]=0.f; acc[j][3]=0.f; }
        #pragma unroll
        for (int ks = 0; ks < 2; ks++) {
            unsigned a0 = f22h2(eaf[4*ks+0].x, eaf[4*ks+0].y);
            unsigned a1 = f22h2(eaf[4*ks+1].x, eaf[4*ks+1].y);
            unsigned a2 = f22h2(eaf[4*ks+2].x, eaf[4*ks+2].y);
            unsigned a3 = f22h2(eaf[4*ks+3].x, eaf[4*ks+3].y);
            #pragma unroll
            for (int blk = 0; blk < 16; blk++) {
                uint2 b = W1t[ks * 512 + (blk >> 2) * 128 + (blk & 3) * 32];
                mma16(acc[blk], a0, a1, a2, a3, b.x, b.y);
            }
        }

        // epi1: tanh in regs -> e frags
        #pragma unroll
        for (int j = 0; j < 16; j++) {
            float2 bb = *(const float2*)(sB1 + j * 8 + 2 * tig);
            ef[2*j]   = f22h2(tanh_mufu(acc[j][0] + bb.x), tanh_mufu(acc[j][1] + bb.y));
            ef[2*j+1] = f22h2(tanh_mufu(acc[j][2] + bb.x), tanh_mufu(acc[j][3] + bb.y));
        }

        // prefetch next chunk: EA frags + indices
        int cn = c + stride;
        int nb = (cn < nchunks ? cn : c) * 16;
        LDG_EA(nb);
        LDIDX(idxv, nb);

        // MMA2: h = e @ W2c2
        #pragma unroll
        for (int j = 0; j < 16; j++) { acc[j][0]=0.f; acc[j][1]=0.f; acc[j][2]=0.f; acc[j][3]=0.f; }
        #pragma unroll
        for (int ks = 0; ks < 8; ks++) {
            #pragma unroll
            for (int blk = 0; blk < 16; blk++) {
                uint2 b = W2t[ks * 512 + (blk >> 2) * 128 + (blk & 3) * 32];
                mma16(acc[blk], ef[4*ks], ef[4*ks+1], ef[4*ks+2], ef[4*ks+3], b.x, b.y);
            }
        }
        CP_WAIT(0);                          // P(cur) done
        __syncwarp();

        // epi2: h = relu((acc + Prow + Pcol)*scale + shift) -> h frags
        #pragma unroll
        for (int j = 0; j < 16; j++) {
            int cc = j * 8 + 2 * tig;
            float2 sc = *(const float2*)(sScale + cc);
            float2 sh = *(const float2*)(sShift + cc);
            int po = j * 16 + tig * 4;
            float2 r0 = h2f2(*(const unsigned*)(smem + (sPR - sb) + gid * PRB + po));
            float2 q0 = h2f2(*(const unsigned*)(smem + (sPC - sb) + gid * PRB + po));
            float2 r1 = h2f2(*(const unsigned*)(smem + (sPR - sb) + (gid + 8) * PRB + po));
            float2 q1 = h2f2(*(const unsigned*)(smem + (sPC - sb) + (gid + 8) * PRB + po));
            ef[2*j] = f22h2(
                fmaxf(fmaf(acc[j][0] + r0.x + q0.x, sc.x, sh.x), 0.f),
                fmaxf(fmaf(acc[j][1] + r0.y + q0.y, sc.y, sh.y), 0.f));
            ef[2*j+1] = f22h2(
                fmaxf(fmaf(acc[j][2] + r1.x + q1.x, sc.x, sh.x), 0.f),
                fmaxf(fmaf(acc[j][3] + r1.y + q1.y, sc.y, sh.y), 0.f));
        }

        // MMA3: y = h @ W3
        #pragma unroll
        for (int j = 0; j < 16; j++) { acc[j][0]=0.f; acc[j][1]=0.f; acc[j][2]=0.f; acc[j][3]=0.f; }
        #pragma unroll
        for (int ks = 0; ks < 8; ks++) {
            #pragma unroll
            for (int blk = 0; blk < 16; blk++) {
                uint2 b = W3t[ks * 512 + (blk >> 2) * 128 + (blk & 3) * 32];
                mma16(acc[blk], ef[4*ks], ef[4*ks+1], ef[4*ks+2], ef[4*ks+3], b.x, b.y);
            }
        }

        // epi3: relu(y + b3) -> gmem
        {
            int e0 = ebase + gid, e1 = ebase + gid + 8;
            float* po0 = out + (long long)e0 * 128;
            float* po1 = out + (long long)e1 * 128;
            #pragma unroll
            for (int j = 0; j < 16; j++) {
                int cc = j * 8 + 2 * tig;
                float2 bb = *(const float2*)(sB3 + cc);
                if (e0 < E) st_cs_v2(po0 + cc, fmaxf(acc[j][0] + bb.x, 0.f),
                                               fmaxf(acc[j][1] + bb.y, 0.f));
                if (e1 < E) st_cs_v2(po1 + cc, fmaxf(acc[j][2] + bb.x, 0.f),
                                               fmaxf(acc[j][3] + bb.y, 0.f));
            }
        }
    }
    CP_WAIT(0);
}

extern "C" void kernel_launch(void* const* d_in, const int* in_sizes, int n_in,
                              void* d_out, int out_size) {
    const float* x     = (const float*)d_in[0];
    const int*   ei    = (const int*)  d_in[1];
    const float* eattr = (const float*)d_in[2];
    const float* W1    = (const float*)d_in[3];
    const float* b1    = (const float*)d_in[4];
    const float* W2    = (const float*)d_in[5];
    const float* b2    = (const float*)d_in[6];
    const float* gam   = (const float*)d_in[7];
    const float* bet   = (const float*)d_in[8];
    const float* mean  = (const float*)d_in[9];
    const float* var   = (const float*)d_in[10];
    const float* W3    = (const float*)d_in[11];
    const float* b3    = (const float*)d_in[12];
    float* out = (float*)d_out;

    int N = in_sizes[0] / 128;
    int E = in_sizes[2] / 32;
    int nchunks = (E + 15) / 16;
    int ntilesN = (N + 127) / 128;

    cudaFuncSetAttribute(node_proj, cudaFuncAttributeMaxDynamicSharedMemorySize, SMEM_N);
    cudaFuncSetAttribute(edge_kernel, cudaFuncAttributeMaxDynamicSharedMemorySize, SMEM_E);

    prep<<<64, 256>>>(W1, W2, W3);
    node_proj<<<148, 512, SMEM_N>>>(x, N, ntilesN);
    edge_kernel<<<148, NT, SMEM_E>>>(ei, eattr, b1, b2, gam, bet,
                                     mean, var, b3, out, E, nchunks);
}

// round 16
// speedup vs baseline: 1.1730x; 1.0200x over previous
#include <cuda_runtime.h>
#include <cuda_fp16.h>

#define NT 384
#define EARB 144           // EA staging row stride (fp32, padded)
#define PRB  272           // P staging row stride
#define WPB  11264         // per-warp staging stride

// ---- edge-kernel smem layout ----
#define OFF_SC 0           // scale,shift,b1,b3 = 2048
#define OFF_W1 2048        // 8192  (1 kstep-pair, uint4 frags)
#define OFF_W2 10240       // 32768 (W2c2: 4 pairs)
#define OFF_W3 43008       // 32768 (W3: 4 pairs)
#define OFF_WP 75776       // 12 warps x 11264 (EA 2304 | PR 4352 | PC 4352)
#define SMEM_E (75776 + 12 * 11264)

// ---- node-kernel smem layout ----
#define ARB  272
#define NOFF_A   0
#define NOFF_W   34816
#define NOFF_XS  100352
#define SMEM_N   165888

__device__ __align__(16) unsigned g_P[131072 * 128];
// paired fragment scratch for edge kernel (uint4 = ksteps 2p, 2p+1)
__device__ __align__(16) uint4 g_W1p[512];
__device__ __align__(16) uint4 g_W2c2p[4 * 512];
__device__ __align__(16) uint4 g_W3p[4 * 512];

#define CP16(dst, src)  asm volatile("cp.async.cg.shared.global [%0], [%1], 16;" :: "r"(dst), "l"(src) : "memory")
#define CP_COMMIT()     asm volatile("cp.async.commit_group;" ::: "memory")
#define CP_WAIT(n)      asm volatile("cp.async.wait_group %0;" :: "n"(n) : "memory")

__device__ __forceinline__ unsigned smem_u32(const void* p) {
    unsigned a;
    asm("{ .reg .u64 t; cvta.to.shared.u64 t, %1; cvt.u32.u64 %0, t; }" : "=r"(a) : "l"(p));
    return a;
}
__device__ __forceinline__ unsigned f22h2(float lo, float hi) {
    unsigned r;
    asm("cvt.rn.f16x2.f32 %0, %1, %2;" : "=r"(r) : "f"(hi), "f"(lo));
    return r;
}
__device__ __forceinline__ float2 h2f2(unsigned u) {
    __half2 h; *(unsigned*)&h = u;
    return __half22float2(h);
}
__device__ __forceinline__ void mma16(float* c, unsigned a0, unsigned a1, unsigned a2,
                                      unsigned a3, unsigned b0, unsigned b1) {
    asm volatile("mma.sync.aligned.m16n8k16.row.col.f32.f16.f16.f32 "
        "{%0,%1,%2,%3}, {%4,%5,%6,%7}, {%8,%9}, {%0,%1,%2,%3};"
        : "+f"(c[0]), "+f"(c[1]), "+f"(c[2]), "+f"(c[3])
        : "r"(a0), "r"(a1), "r"(a2), "r"(a3), "r"(b0), "r"(b1));
}
__device__ __forceinline__ float tanh_mufu(float v) {
    float r;
    asm("tanh.approx.f32 %0, %1;" : "=f"(r) : "f"(v));
    return r;
}
__device__ __forceinline__ void st_cs_v2(float* p, float a, float b) {
    asm volatile("st.global.cs.v2.f32 [%0], {%1,%2};" :: "l"(p), "f"(a), "f"(b) : "memory");
}

// fragment for (W, lane, nt, cq, kstep): uint2 of fp16x2
__device__ __forceinline__ uint2 mk_frag(const float* W, int lane, int nt, int cq, int ks) {
    int n = cq * 32 + nt * 8 + (lane >> 2), k0 = ks * 16 + (lane & 3) * 2;
    return make_uint2(f22h2(W[k0 * 128 + n], W[(k0 + 1) * 128 + n]),
                      f22h2(W[(k0 + 8) * 128 + n], W[(k0 + 9) * 128 + n]));
}

// ---- node projections: persistent; also produces edge-kernel weight scratch ----
__global__ void __launch_bounds__(512, 1)
node_proj(const float* __restrict__ x, const float* __restrict__ W1,
          const float* __restrict__ W2, const float* __restrict__ W3,
          int N, int ntilesN) {
    extern __shared__ char smem[];
    const unsigned sb = smem_u32(smem);
    const int tid = threadIdx.x;
    const int w = tid >> 5, lane = tid & 31;
    const int gid = lane >> 2, tig = lane & 3;
    const int rb = (w >> 2) * 32, cq = w & 3, cbase = cq * 32;
    const int r4 = tid >> 2, q4 = tid & 3;

    // compute own W2 c0+c1 frags (ksteps 0..15) into smem
    for (int i = tid; i < 16 * 512; i += 512) {
        int l = i & 31, nt = (i >> 5) & 3, c = (i >> 7) & 3, ks = i >> 9;
        *(uint2*)(smem + NOFF_W + i * 8) = mk_frag(W2, l, nt, c, ks);
    }
    // block 0 writes paired global frags for the edge kernel
    if (blockIdx.x == 0) {
        for (int j = tid; j < 512; j += 512) {
            int l = j & 31, nt = (j >> 5) & 3, c = (j >> 7) & 3;
            uint2 f0 = mk_frag(W1, l, nt, c, 0), f1 = mk_frag(W1, l, nt, c, 1);
            g_W1p[j] = make_uint4(f0.x, f0.y, f1.x, f1.y);
        }
        for (int j = tid; j < 2048; j += 512) {
            int l = j & 31, nt = (j >> 5) & 3, c = (j >> 7) & 3, p = j >> 9;
            uint2 f0 = mk_frag(W2, l, nt, c, 16 + 2 * p);
            uint2 f1 = mk_frag(W2, l, nt, c, 16 + 2 * p + 1);
            g_W2c2p[j] = make_uint4(f0.x, f0.y, f1.x, f1.y);
        }
        for (int j = tid; j < 2048; j += 512) {
            int l = j & 31, nt = (j >> 5) & 3, c = (j >> 7) & 3, p = j >> 9;
            uint2 f0 = mk_frag(W3, l, nt, c, 2 * p), f1 = mk_frag(W3, l, nt, c, 2 * p + 1);
            g_W3p[j] = make_uint4(f0.x, f0.y, f1.x, f1.y);
        }
    }
    __syncthreads();

    const char* Ath = smem + NOFF_A + (rb + gid) * ARB + tig * 4;
    const uint2* Wt = (const uint2*)(smem + NOFF_W) + cq * 128 + lane;

    for (int tile = blockIdx.x; tile < ntilesN; tile += gridDim.x) {
        {
            int node = min(tile * 128 + r4, N - 1);
            const float* s = x + (long long)node * 128 + q4 * 32;
            unsigned d = sb + NOFF_XS + (r4 * 128 + q4 * 32) * 4;
            #pragma unroll
            for (int i = 0; i < 8; i++) CP16(d + i * 16, s + i * 4);
        }
        CP_COMMIT(); CP_WAIT(0);
        __syncthreads();
        {
            const float* s = (const float*)(smem + NOFF_XS) + r4 * 128 + q4 * 32;
            unsigned* d = (unsigned*)(smem + NOFF_A + r4 * ARB) + q4 * 16;
            #pragma unroll
            for (int i = 0; i < 16; i++) d[i] = f22h2(s[2 * i], s[2 * i + 1]);
        }
        __syncthreads();

        float acc[2][4][4];
        #pragma unroll
        for (int ch = 0; ch < 2; ch++) {
            #pragma unroll
            for (int m = 0; m < 2; m++)
                #pragma unroll
                for (int n = 0; n < 4; n++)
                    { acc[m][n][0]=0.f; acc[m][n][1]=0.f; acc[m][n][2]=0.f; acc[m][n][3]=0.f; }
            #pragma unroll
            for (int ks = 0; ks < 8; ks++) {
                unsigned a[2][4];
                #pragma unroll
                for (int mt = 0; mt < 2; mt++) {
                    const char* Am = Ath + ks * 32 + mt * 16 * ARB;
                    a[mt][0] = *(const unsigned*)(Am);
                    a[mt][1] = *(const unsigned*)(Am + 8 * ARB);
                    a[mt][2] = *(const unsigned*)(Am + 16);
                    a[mt][3] = *(const unsigned*)(Am + 8 * ARB + 16);
                }
                const uint2* Bk = Wt + (ch * 8 + ks) * 512;
                #pragma unroll
                for (int nt = 0; nt < 4; nt++) {
                    uint2 b = Bk[nt * 32];
                    mma16(acc[0][nt], a[0][0], a[0][1], a[0][2], a[0][3], b.x, b.y);
                    mma16(acc[1][nt], a[1][0], a[1][1], a[1][2], a[1][3], b.x, b.y);
                }
            }
            #pragma unroll
            for (int mt = 0; mt < 2; mt++) {
                int node0 = tile * 128 + rb + mt * 16 + gid;
                int pcol = ch * 64 + (cbase >> 1) + tig;
                #pragma unroll
                for (int nt = 0; nt < 4; nt++) {
                    if (node0 < N)
                        g_P[(long long)node0 * 128 + pcol + nt * 4] =
                            f22h2(acc[mt][nt][0], acc[mt][nt][1]);
                    if (node0 + 8 < N)
                        g_P[(long long)(node0 + 8) * 128 + pcol + nt * 4] =
                            f22h2(acc[mt][nt][2], acc[mt][nt][3]);
                }
            }
        }
        __syncthreads();
    }
}

// ---- edge kernel: 12 warps, barrier-free per-warp streams, paired B-frag LDS.128 ----
__global__ void __launch_bounds__(NT, 1)
edge_kernel(const int* __restrict__ ei, const float* __restrict__ ea,
            const float* __restrict__ b1, const float* __restrict__ b2,
            const float* __restrict__ gamma, const float* __restrict__ beta,
            const float* __restrict__ mean, const float* __restrict__ var,
            const float* __restrict__ b3,
            float* __restrict__ out, int E, int nchunks)
{
    extern __shared__ char smem[];
    const unsigned sb = smem_u32(smem);
    float* sScale = (float*)(smem + OFF_SC);
    float* sShift = (float*)(smem + OFF_SC + 512);
    float* sB1    = (float*)(smem + OFF_SC + 1024);
    float* sB3    = (float*)(smem + OFF_SC + 1536);

    const int tid = threadIdx.x;
    const int w = tid >> 5, lane = tid & 31;
    const int gid = lane >> 2, tig = lane & 3;
    const int l16 = lane & 15, lh = lane >> 4;

    if (tid < 128) {
        float sc = gamma[tid] * rsqrtf(var[tid] + 1e-5f);
        sScale[tid] = sc;
        sShift[tid] = (b2[tid] - mean[tid]) * sc + beta[tid];
        sB1[tid] = b1[tid];
        sB3[tid] = b3[tid];
    }
    for (int i = tid; i < 512; i += NT)
        CP16(sb + OFF_W1 + i * 16, (const char*)g_W1p + i * 16);
    for (int i = tid; i < 2048; i += NT)
        CP16(sb + OFF_W2 + i * 16, (const char*)g_W2c2p + i * 16);
    for (int i = tid; i < 2048; i += NT)
        CP16(sb + OFF_W3 + i * 16, (const char*)g_W3p + i * 16);
    CP_COMMIT(); CP_WAIT(0);
    __syncthreads();

    const bool is64 = ((ei[1] | ei[3] | ei[5] | ei[7]) == 0);
    const long long* ei64 = (const long long*)ei;

    // per-warp staging
    const unsigned wp = sb + OFF_WP + w * WPB;
    const unsigned sEA = wp;             // 16 x EARB fp32
    const unsigned sPR = wp + 2304;      // 16 x PRB
    const unsigned sPC = wp + 6656;      // 16 x PRB
    const uint4* W1t = (const uint4*)(smem + OFF_W1) + lane;
    const uint4* W2t = (const uint4*)(smem + OFF_W2) + lane;
    const uint4* W3t = (const uint4*)(smem + OFF_W3) + lane;

    #define LDIDX(dst, eb) { int _e = min((eb) + l16, E - 1); \
        long long _o = (lane < 16) ? (long long)_e : (long long)E + _e; \
        (dst) = is64 ? (int)ei64[_o] : ei[_o]; }
    #define ISSUE_EA(eb) { int _ge = min((eb) + l16, E - 1); \
        const float* _s = ea + (long long)_ge * 32 + lh * 16; \
        unsigned _d = sEA + l16 * EARB + lh * 64; \
        CP16(_d, _s); CP16(_d + 16, _s + 4); \
        CP16(_d + 32, _s + 8); CP16(_d + 48, _s + 12); CP_COMMIT(); }

    const int stride = gridDim.x * 12;
    const int c0 = blockIdx.x * 12 + w;

    int idxv;
    LDIDX(idxv, c0 * 16);
    ISSUE_EA(c0 * 16);                       // group: EA(cur)

    float acc[16][4];
    unsigned ef[32];

    for (int c = c0; c < nchunks; c += stride) {
        const int ebase = c * 16;

        // issue P gather for cur (uses idxv via shfl)
        {
            int nR = __shfl_sync(0xffffffffu, idxv, l16);
            int nC = __shfl_sync(0xffffffffu, idxv, 16 + l16);
            const char* srcR = (const char*)g_P + (long long)nR * 512 + lh * 128;
            const char* srcC = (const char*)g_P + (long long)nC * 512 + 256 + lh * 128;
            unsigned dR = sPR + l16 * PRB + lh * 128;
            unsigned dC = sPC + l16 * PRB + lh * 128;
            #pragma unroll
            for (int i = 0; i < 8; i++) CP16(dR + i * 16, srcR + i * 16);
            #pragma unroll
            for (int i = 0; i < 8; i++) CP16(dC + i * 16, srcC + i * 16);
            CP_COMMIT();                     // group: P(cur)
        }
        CP_WAIT(1);                          // EA(cur) done (P outstanding)
        __syncwarp();

        // MMA1: e = EA @ W1 (K=32), both kstep a-frags first, paired B loads
        #pragma unroll
        for (int j = 0; j < 16; j++) { acc[j][0]=0.f; acc[j][1]=0.f; acc[j][2]=0.f; acc[j][3]=0.f; }
        {
            unsigned a[2][4];
            #pragma unroll
            for (int ks = 0; ks < 2; ks++) {
                const char* Ak = (const char*)smem + (sEA - sb) + ks * 64 + tig * 8;
                float2 v0 = *(const float2*)(Ak + gid * EARB);
                float2 v1 = *(const float2*)(Ak + (gid + 8) * EARB);
                float2 v2 = *(const float2*)(Ak + gid * EARB + 32);
                float2 v3 = *(const float2*)(Ak + (gid + 8) * EARB + 32);
                a[ks][0] = f22h2(v0.x, v0.y); a[ks][1] = f22h2(v1.x, v1.y);
                a[ks][2] = f22h2(v2.x, v2.y); a[ks][3] = f22h2(v3.x, v3.y);
            }
            #pragma unroll
            for (int blk = 0; blk < 16; blk++) {
                uint4 b = W1t[(blk >> 2) * 128 + (blk & 3) * 32];
                mma16(acc[blk], a[0][0], a[0][1], a[0][2], a[0][3], b.x, b.y);
                mma16(acc[blk], a[1][0], a[1][1], a[1][2], a[1][3], b.z, b.w);
            }
        }

        // epi1: tanh in regs -> e frags
        #pragma unroll
        for (int j = 0; j < 16; j++) {
            float2 bb = *(const float2*)(sB1 + j * 8 + 2 * tig);
            ef[2*j]   = f22h2(tanh_mufu(acc[j][0] + bb.x), tanh_mufu(acc[j][1] + bb.y));
            ef[2*j+1] = f22h2(tanh_mufu(acc[j][2] + bb.x), tanh_mufu(acc[j][3] + bb.y));
        }

        // prefetch next chunk: EA + indices
        int cn = c + stride;
        int nb = (cn < nchunks ? cn : c) * 16;
        ISSUE_EA(nb);                        // group: EA(next)
        LDIDX(idxv, nb);

        // MMA2: h = e @ W2c2 (4 kstep-pairs, LDS.128)
        #pragma unroll
        for (int j = 0; j < 16; j++) { acc[j][0]=0.f; acc[j][1]=0.f; acc[j][2]=0.f; acc[j][3]=0.f; }
        #pragma unroll
        for (int p = 0; p < 4; p++) {
            #pragma unroll
            for (int blk = 0; blk < 16; blk++) {
                uint4 b = W2t[p * 512 + (blk >> 2) * 128 + (blk & 3) * 32];
                mma16(acc[blk], ef[8*p+0], ef[8*p+1], ef[8*p+2], ef[8*p+3], b.x, b.y);
                mma16(acc[blk], ef[8*p+4], ef[8*p+5], ef[8*p+6], ef[8*p+7], b.z, b.w);
            }
        }
        CP_WAIT(1);                          // P(cur) done (EA(next) outstanding)
        __syncwarp();

        // epi2: h = relu((acc + Prow + Pcol)*scale + shift) in regs -> h frags
        #pragma unroll
        for (int j = 0; j < 16; j++) {
            int cc = j * 8 + 2 * tig;
            float2 sc = *(const float2*)(sScale + cc);
            float2 sh = *(const float2*)(sShift + cc);
            int po = j * 16 + tig * 4;
            float2 r0 = h2f2(*(const unsigned*)(smem + (sPR - sb) + gid * PRB + po));
            float2 q0 = h2f2(*(const unsigned*)(smem + (sPC - sb) + gid * PRB + po));
            float2 r1 = h2f2(*(const unsigned*)(smem + (sPR - sb) + (gid + 8) * PRB + po));
            float2 q1 = h2f2(*(const unsigned*)(smem + (sPC - sb) + (gid + 8) * PRB + po));
            ef[2*j] = f22h2(
                fmaxf(fmaf(acc[j][0] + r0.x + q0.x, sc.x, sh.x), 0.f),
                fmaxf(fmaf(acc[j][1] + r0.y + q0.y, sc.y, sh.y), 0.f));
            ef[2*j+1] = f22h2(
                fmaxf(fmaf(acc[j][2] + r1.x + q1.x, sc.x, sh.x), 0.f),
                fmaxf(fmaf(acc[j][3] + r1.y + q1.y, sc.y, sh.y), 0.f));
        }

        // MMA3: y = h @ W3 (paired)
        #pragma unroll
        for (int j = 0; j < 16; j++) { acc[j][0]=0.f; acc[j][1]=0.f; acc[j][2]=0.f; acc[j][3]=0.f; }
        #pragma unroll
        for (int p = 0; p < 4; p++) {
            #pragma unroll
            for (int blk = 0; blk < 16; blk++) {
                uint4 b = W3t[p * 512 + (blk >> 2) * 128 + (blk & 3) * 32];
                mma16(acc[blk], ef[8*p+0], ef[8*p+1], ef[8*p+2], ef[8*p+3], b.x, b.y);
                mma16(acc[blk], ef[8*p+4], ef[8*p+5], ef[8*p+6], ef[8*p+7], b.z, b.w);
            }
        }

        // epi3: relu(y + b3) -> gmem
        {
            int e0 = ebase + gid, e1 = ebase + gid + 8;
            float* po0 = out + (long long)e0 * 128;
            float* po1 = out + (long long)e1 * 128;
            #pragma unroll
            for (int j = 0; j < 16; j++) {
                int cc = j * 8 + 2 * tig;
                float2 bb = *(const float2*)(sB3 + cc);
                if (e0 < E) st_cs_v2(po0 + cc, fmaxf(acc[j][0] + bb.x, 0.f),
                                               fmaxf(acc[j][1] + bb.y, 0.f));
                if (e1 < E) st_cs_v2(po1 + cc, fmaxf(acc[j][2] + bb.x, 0.f),
                                               fmaxf(acc[j][3] + bb.y, 0.f));
            }
        }
    }
    CP_WAIT(0);
}

extern "C" void kernel_launch(void* const* d_in, const int* in_sizes, int n_in,
                              void* d_out, int out_size) {
    const float* x     = (const float*)d_in[0];
    const int*   ei    = (const int*)  d_in[1];
    const float* eattr = (const float*)d_in[2];
    const float* W1    = (const float*)d_in[3];
    const float* b1    = (const float*)d_in[4];
    const float* W2    = (const float*)d_in[5];
    const float* b2    = (const float*)d_in[6];
    const float* gam   = (const float*)d_in[7];
    const float* bet   = (const float*)d_in[8];
    const float* mean  = (const float*)d_in[9];
    const float* var   = (const float*)d_in[10];
    const float* W3    = (const float*)d_in[11];
    const float* b3    = (const float*)d_in[12];
    float* out = (float*)d_out;

    int N = in_sizes[0] / 128;
    int E = in_sizes[2] / 32;
    int nchunks = (E + 15) / 16;
    int ntilesN = (N + 127) / 128;

    cudaFuncSetAttribute(node_proj, cudaFuncAttributeMaxDynamicSharedMemorySize, SMEM_N);
    cudaFuncSetAttribute(edge_kernel, cudaFuncAttributeMaxDynamicSharedMemorySize, SMEM_E);

    node_proj<<<148, 512, SMEM_N>>>(x, W1, W2, W3, N, ntilesN);
    edge_kernel<<<148, NT, SMEM_E>>>(ei, eattr, b1, b2, gam, bet,
                                     mean, var, b3, out, E, nchunks);
}